// round 1
// baseline (speedup 1.0000x reference)
#include <cuda_runtime.h>

#define L 512
#define N_ROWS (L * L)          // 262144 rows (i,j) or (i,k)
#define C 128
#define NC (N_ROWS * C)         // 33,554,432 elements

// ---------------- scratch (device globals; no allocations allowed) ----------
__device__ float g_zn[NC];      // z_norm [row][c]
__device__ float g_p[NC];       // projection (pre-gate) [row][c]
__device__ float g_g[NC];       // gate-input projection [row][c]
__device__ float g_gate[NC];    // sigmoid(z Wg^T + bg) [row][c]
__device__ float g_at[NC];      // a transposed: [c][i*512+k]
__device__ float g_bt[NC];      // b transposed: [c][j*512+k]
__device__ float g_xt[NC];      // x transposed: [c][i*512+j]
__device__ float g_mu[N_ROWS];
__device__ float g_rs[N_ROWS];
__device__ float g_rsq[N_ROWS]; // 1/sqrt(max(valid_k,1))

__device__ __forceinline__ float sigm(float x) { return 1.f / (1.f + __expf(-x)); }

// ---------------- K1: input LayerNorm --------------------------------------
__global__ void k_ln_in(const float* __restrict__ z, const float* __restrict__ g,
                        const float* __restrict__ b) {
    int row = blockIdx.x;
    int c = threadIdx.x;   // 128 threads
    float v = z[(size_t)row * C + c];
    __shared__ float s1[128], s2[128];
    s1[c] = v; s2[c] = v * v;
    __syncthreads();
    #pragma unroll
    for (int o = 64; o > 0; o >>= 1) {
        if (c < o) { s1[c] += s1[c + o]; s2[c] += s2[c + o]; }
        __syncthreads();
    }
    float mu = s1[0] * (1.f / 128.f);
    float var = s2[0] * (1.f / 128.f) - mu * mu;
    float rs = rsqrtf(var + 1e-5f);
    g_zn[(size_t)row * C + c] = (v - mu) * rs * g[c] + b[c];
}

// ---------------- K2: projection GEMM Y = act(zn @ W^T + bias) --------------
// BM=64 rows x BN=128 h, K=128 fully staged. 256 threads, 4x8 micro-tile.
// dst: 0 -> g_p, 1 -> g_g, 2 -> g_gate
#define XS_PITCH 68
#define WS_PITCH 132
#define SMEM_GEMM ((128 * XS_PITCH + 128 * WS_PITCH + 128) * 4)

__global__ __launch_bounds__(256) void k_gemm(const float* __restrict__ W,
                                              const float* __restrict__ bias,
                                              int act, int dst) {
    extern __shared__ float sm[];
    float* xs = sm;                        // [128][68]  (c-major)
    float* ws = sm + 128 * XS_PITCH;       // [128][132] (c-major)
    float* bs = ws + 128 * WS_PITCH;       // [128]
    int tid = threadIdx.x;
    int r0 = blockIdx.x * 64;
    const float* X = g_zn;
    float* Y = (dst == 0) ? g_p : (dst == 1) ? g_g : g_gate;

    #pragma unroll
    for (int it = 0; it < 8; it++) {       // X tile: 64 rows x 128 c
        int idx = tid + it * 256;
        int r = idx >> 5; int c4 = (idx & 31) << 2;
        float4 v = *(const float4*)&X[(size_t)(r0 + r) * C + c4];
        xs[(c4 + 0) * XS_PITCH + r] = v.x;
        xs[(c4 + 1) * XS_PITCH + r] = v.y;
        xs[(c4 + 2) * XS_PITCH + r] = v.z;
        xs[(c4 + 3) * XS_PITCH + r] = v.w;
    }
    #pragma unroll
    for (int it = 0; it < 16; it++) {      // W: 128 h x 128 c -> ws[c][h]
        int idx = tid + it * 256;
        int h = idx >> 5; int c4 = (idx & 31) << 2;
        float4 v = *(const float4*)&W[h * C + c4];
        ws[(c4 + 0) * WS_PITCH + h] = v.x;
        ws[(c4 + 1) * WS_PITCH + h] = v.y;
        ws[(c4 + 2) * WS_PITCH + h] = v.z;
        ws[(c4 + 3) * WS_PITCH + h] = v.w;
    }
    if (tid < 128) bs[tid] = bias[tid];
    __syncthreads();

    int tx = tid & 15, ty = tid >> 4;
    int h0 = tx * 8, rb = ty * 4;
    float acc[4][8];
    #pragma unroll
    for (int i = 0; i < 4; i++)
        #pragma unroll
        for (int j = 0; j < 8; j++) acc[i][j] = 0.f;

    #pragma unroll 4
    for (int c = 0; c < C; c++) {
        float4 xv = *(float4*)&xs[c * XS_PITCH + rb];
        float4 wa = *(float4*)&ws[c * WS_PITCH + h0];
        float4 wb = *(float4*)&ws[c * WS_PITCH + h0 + 4];
        float xr[4] = {xv.x, xv.y, xv.z, xv.w};
        float wr[8] = {wa.x, wa.y, wa.z, wa.w, wb.x, wb.y, wb.z, wb.w};
        #pragma unroll
        for (int i = 0; i < 4; i++)
            #pragma unroll
            for (int j = 0; j < 8; j++) acc[i][j] = fmaf(xr[i], wr[j], acc[i][j]);
    }

    #pragma unroll
    for (int i = 0; i < 4; i++) {
        int row = r0 + rb + i;
        float o[8];
        #pragma unroll
        for (int j = 0; j < 8; j++) {
            float v = acc[i][j] + bs[h0 + j];
            o[j] = act ? sigm(v) : v;
        }
        *(float4*)&Y[(size_t)row * C + h0]     = make_float4(o[0], o[1], o[2], o[3]);
        *(float4*)&Y[(size_t)row * C + h0 + 4] = make_float4(o[4], o[5], o[6], o[7]);
    }
}

// ---------------- K3: combine p*sigm(g)*mask + transpose to [c][row] --------
__global__ void k_combine_t(const float* __restrict__ mask, int dst) {
    __shared__ float t[32][33];
    const float* P = g_p;
    const float* G = g_g;
    float* AT = dst ? g_bt : g_at;
    int r0 = blockIdx.x * 32, c0 = blockIdx.y * 32;
    int tx = threadIdx.x, ty = threadIdx.y;  // 32 x 8
    #pragma unroll
    for (int s = 0; s < 4; s++) {
        int r = r0 + ty + s * 8;
        float p = P[(size_t)r * C + c0 + tx];
        float gg = G[(size_t)r * C + c0 + tx];
        t[ty + s * 8][tx] = p * sigm(gg) * mask[r];
    }
    __syncthreads();
    #pragma unroll
    for (int s = 0; s < 4; s++) {
        int c = c0 + ty + s * 8;
        AT[(size_t)c * N_ROWS + r0 + tx] = t[tx][ty + s * 8];
    }
}

// ---------------- K4: rsq[i][j] = 1/sqrt(max(sum_k m[i,k]m[j,k],1)) ---------
__global__ void k_rsq(const float* __restrict__ mask) {
    __shared__ float mi[8][512];
    int i0 = blockIdx.x * 8;
    int tid = threadIdx.x;
    for (int idx = tid; idx < 8 * 512; idx += 256)
        mi[idx >> 9][idx & 511] = mask[(size_t)(i0 + (idx >> 9)) * L + (idx & 511)];
    __syncthreads();
    for (int j = tid; j < L; j += 256) {
        float s[8];
        #pragma unroll
        for (int ii = 0; ii < 8; ii++) s[ii] = 0.f;
        for (int k = 0; k < L; k += 4) {
            float4 m4 = *(const float4*)&mask[(size_t)j * L + k];
            float mv[4] = {m4.x, m4.y, m4.z, m4.w};
            #pragma unroll
            for (int q = 0; q < 4; q++)
                #pragma unroll
                for (int ii = 0; ii < 8; ii++) s[ii] = fmaf(mi[ii][k + q], mv[q], s[ii]);
        }
        #pragma unroll
        for (int ii = 0; ii < 8; ii++)
            g_rsq[(size_t)(i0 + ii) * L + j] = rsqrtf(fmaxf(s[ii], 1.f));
    }
}

// ---------------- K5: triangle contraction per channel ----------------------
// x_t[c][i][j] = rsq[i][j] * sum_k a_t[c][i][k] * b_t[c][j][k]
// 128x128 tile per block per channel; thread: 8i x 8j; double-buffered smem.
__global__ __launch_bounds__(256, 2) void k_tri() {
    __shared__ float as_[2][8][128];
    __shared__ float bs_[2][8][128];
    int c = blockIdx.z;
    int i0 = blockIdx.y * 128, j0 = blockIdx.x * 128;
    const float* A = g_at + (size_t)c * N_ROWS + (size_t)i0 * L;
    const float* B = g_bt + (size_t)c * N_ROWS + (size_t)j0 * L;
    int tid = threadIdx.x;
    int li = tid >> 1;                  // 0..127
    int kq = (tid & 1) * 4;             // 0 or 4
    int tx = tid & 15, ty = tid >> 4;   // tx -> j groups, ty -> i groups

    float acc[8][8];
    #pragma unroll
    for (int i = 0; i < 8; i++)
        #pragma unroll
        for (int j = 0; j < 8; j++) acc[i][j] = 0.f;

    {   // preload chunk 0
        float4 pa = *(const float4*)&A[li * L + kq];
        float4 pb = *(const float4*)&B[li * L + kq];
        as_[0][kq + 0][li] = pa.x; as_[0][kq + 1][li] = pa.y;
        as_[0][kq + 2][li] = pa.z; as_[0][kq + 3][li] = pa.w;
        bs_[0][kq + 0][li] = pb.x; bs_[0][kq + 1][li] = pb.y;
        bs_[0][kq + 2][li] = pb.z; bs_[0][kq + 3][li] = pb.w;
    }
    __syncthreads();

    for (int kb = 0; kb < 64; kb++) {
        float4 na, nb;
        bool pre = kb < 63;
        if (pre) {
            na = *(const float4*)&A[li * L + (kb + 1) * 8 + kq];
            nb = *(const float4*)&B[li * L + (kb + 1) * 8 + kq];
        }
        int cur = kb & 1;
        #pragma unroll
        for (int kk = 0; kk < 8; kk++) {
            float4 a0 = *(float4*)&as_[cur][kk][ty * 4];
            float4 a1 = *(float4*)&as_[cur][kk][64 + ty * 4];
            float4 b0 = *(float4*)&bs_[cur][kk][tx * 4];
            float4 b1 = *(float4*)&bs_[cur][kk][64 + tx * 4];
            float av[8] = {a0.x, a0.y, a0.z, a0.w, a1.x, a1.y, a1.z, a1.w};
            float bv[8] = {b0.x, b0.y, b0.z, b0.w, b1.x, b1.y, b1.z, b1.w};
            #pragma unroll
            for (int i = 0; i < 8; i++)
                #pragma unroll
                for (int j = 0; j < 8; j++)
                    acc[i][j] = fmaf(av[i], bv[j], acc[i][j]);
        }
        if (pre) {
            int nxt = cur ^ 1;
            as_[nxt][kq + 0][li] = na.x; as_[nxt][kq + 1][li] = na.y;
            as_[nxt][kq + 2][li] = na.z; as_[nxt][kq + 3][li] = na.w;
            bs_[nxt][kq + 0][li] = nb.x; bs_[nxt][kq + 1][li] = nb.y;
            bs_[nxt][kq + 2][li] = nb.z; bs_[nxt][kq + 3][li] = nb.w;
        }
        __syncthreads();
    }

    #pragma unroll
    for (int ia = 0; ia < 8; ia++) {
        int il = (ia < 4) ? (ty * 4 + ia) : (64 + ty * 4 + ia - 4);
        size_t rowoff = (size_t)(i0 + il) * L + j0;
        float4 rq0 = *(const float4*)&g_rsq[rowoff + tx * 4];
        float4 rq1 = *(const float4*)&g_rsq[rowoff + 64 + tx * 4];
        float4 o0 = make_float4(acc[ia][0] * rq0.x, acc[ia][1] * rq0.y,
                                acc[ia][2] * rq0.z, acc[ia][3] * rq0.w);
        float4 o1 = make_float4(acc[ia][4] * rq1.x, acc[ia][5] * rq1.y,
                                acc[ia][6] * rq1.z, acc[ia][7] * rq1.w);
        float* xp = &g_xt[(size_t)c * N_ROWS + rowoff];
        *(float4*)&xp[tx * 4] = o0;
        *(float4*)&xp[64 + tx * 4] = o1;
    }
}

// ---------------- K6: LN-out stats over x_t ---------------------------------
__global__ void k_lnstats() {
    int row = blockIdx.x * 256 + threadIdx.x;
    float s = 0.f, s2 = 0.f;
    #pragma unroll 4
    for (int c = 0; c < C; c++) {
        float v = g_xt[(size_t)c * N_ROWS + row];
        s += v; s2 += v * v;
    }
    float mu = s * (1.f / 128.f);
    float var = s2 * (1.f / 128.f) - mu * mu;
    g_mu[row] = mu;
    g_rs[row] = rsqrtf(var + 1e-5f);
}

// ---------------- K7: final GEMM with fused LN-in-staging + gated epilogue --
#define SMEM_GEMM2 ((128 * XS_PITCH + 128 * WS_PITCH + 128 + 64 + 64 + 128 + 128) * 4)

__global__ __launch_bounds__(256) void k_gemm_out(const float* __restrict__ Wo,
                                                  const float* __restrict__ bo,
                                                  const float* __restrict__ lng,
                                                  const float* __restrict__ lnb,
                                                  const float* __restrict__ mask,
                                                  float* __restrict__ OUT) {
    extern __shared__ float sm[];
    float* xs  = sm;                       // [128][68]
    float* ws  = sm + 128 * XS_PITCH;      // [128][132]
    float* bs  = ws + 128 * WS_PITCH;      // 128
    float* mus = bs + 128;                 // 64
    float* rss = mus + 64;                 // 64
    float* lgs = rss + 64;                 // 128
    float* lbs = lgs + 128;                // 128
    int tid = threadIdx.x;
    int r0 = blockIdx.x * 64;

    if (tid < 64) { mus[tid] = g_mu[r0 + tid]; rss[tid] = g_rs[r0 + tid]; }
    if (tid < 128) { lgs[tid] = lng[tid]; lbs[tid] = lnb[tid]; bs[tid] = bo[tid]; }
    __syncthreads();

    #pragma unroll
    for (int it = 0; it < 8; it++) {       // X tile from x_t with LN applied
        int idx = tid + it * 256;          // 128 c * 16 groups of 4 rows
        int cc = idx >> 4; int rq = (idx & 15) << 2;
        float4 v = *(const float4*)&g_xt[(size_t)cc * N_ROWS + r0 + rq];
        float gsc = lgs[cc], bsc = lbs[cc];
        xs[cc * XS_PITCH + rq + 0] = (v.x - mus[rq + 0]) * rss[rq + 0] * gsc + bsc;
        xs[cc * XS_PITCH + rq + 1] = (v.y - mus[rq + 1]) * rss[rq + 1] * gsc + bsc;
        xs[cc * XS_PITCH + rq + 2] = (v.z - mus[rq + 2]) * rss[rq + 2] * gsc + bsc;
        xs[cc * XS_PITCH + rq + 3] = (v.w - mus[rq + 3]) * rss[rq + 3] * gsc + bsc;
    }
    #pragma unroll
    for (int it = 0; it < 16; it++) {      // Wo: 128 out x 128 in -> ws[c][h]
        int idx = tid + it * 256;
        int h = idx >> 5; int c4 = (idx & 31) << 2;
        float4 v = *(const float4*)&Wo[h * C + c4];
        ws[(c4 + 0) * WS_PITCH + h] = v.x;
        ws[(c4 + 1) * WS_PITCH + h] = v.y;
        ws[(c4 + 2) * WS_PITCH + h] = v.z;
        ws[(c4 + 3) * WS_PITCH + h] = v.w;
    }
    __syncthreads();

    int tx = tid & 15, ty = tid >> 4;
    int h0 = tx * 8, rb = ty * 4;
    float acc[4][8];
    #pragma unroll
    for (int i = 0; i < 4; i++)
        #pragma unroll
        for (int j = 0; j < 8; j++) acc[i][j] = 0.f;

    #pragma unroll 4
    for (int c = 0; c < C; c++) {
        float4 xv = *(float4*)&xs[c * XS_PITCH + rb];
        float4 wa = *(float4*)&ws[c * WS_PITCH + h0];
        float4 wb = *(float4*)&ws[c * WS_PITCH + h0 + 4];
        float xr[4] = {xv.x, xv.y, xv.z, xv.w};
        float wr[8] = {wa.x, wa.y, wa.z, wa.w, wb.x, wb.y, wb.z, wb.w};
        #pragma unroll
        for (int i = 0; i < 4; i++)
            #pragma unroll
            for (int j = 0; j < 8; j++) acc[i][j] = fmaf(xr[i], wr[j], acc[i][j]);
    }

    #pragma unroll
    for (int i = 0; i < 4; i++) {
        int row = r0 + rb + i;
        float m = mask[row];
        float4 gg0 = *(const float4*)&g_gate[(size_t)row * C + h0];
        float4 gg1 = *(const float4*)&g_gate[(size_t)row * C + h0 + 4];
        float4 o0 = make_float4((acc[i][0] + bs[h0 + 0]) * gg0.x * m,
                                (acc[i][1] + bs[h0 + 1]) * gg0.y * m,
                                (acc[i][2] + bs[h0 + 2]) * gg0.z * m,
                                (acc[i][3] + bs[h0 + 3]) * gg0.w * m);
        float4 o1 = make_float4((acc[i][4] + bs[h0 + 4]) * gg1.x * m,
                                (acc[i][5] + bs[h0 + 5]) * gg1.y * m,
                                (acc[i][6] + bs[h0 + 6]) * gg1.z * m,
                                (acc[i][7] + bs[h0 + 7]) * gg1.w * m);
        *(float4*)&OUT[(size_t)row * C + h0]     = o0;
        *(float4*)&OUT[(size_t)row * C + h0 + 4] = o1;
    }
}

// ---------------- launch -----------------------------------------------------
extern "C" void kernel_launch(void* const* d_in, const int* in_sizes, int n_in,
                              void* d_out, int out_size) {
    const float* z       = (const float*)d_in[0];
    const float* mask    = (const float*)d_in[1];
    const float* ln_in_g = (const float*)d_in[2];
    const float* ln_in_b = (const float*)d_in[3];
    const float* Wap = (const float*)d_in[4],  *bap = (const float*)d_in[5];
    const float* Wbp = (const float*)d_in[6],  *bbp = (const float*)d_in[7];
    const float* Wag = (const float*)d_in[8],  *bag = (const float*)d_in[9];
    const float* Wbg = (const float*)d_in[10], *bbg = (const float*)d_in[11];
    const float* lng = (const float*)d_in[12], *lnb = (const float*)d_in[13];
    const float* Wo  = (const float*)d_in[14], *bo  = (const float*)d_in[15];
    const float* Wg  = (const float*)d_in[16], *bg  = (const float*)d_in[17];
    float* out = (float*)d_out;

    cudaFuncSetAttribute(k_gemm, cudaFuncAttributeMaxDynamicSharedMemorySize, SMEM_GEMM);
    cudaFuncSetAttribute(k_gemm_out, cudaFuncAttributeMaxDynamicSharedMemorySize, SMEM_GEMM2);

    k_ln_in<<<N_ROWS, 128>>>(z, ln_in_g, ln_in_b);

    k_gemm<<<4096, 256, SMEM_GEMM>>>(Wap, bap, 0, 0);
    k_gemm<<<4096, 256, SMEM_GEMM>>>(Wag, bag, 0, 1);
    k_combine_t<<<dim3(N_ROWS / 32, 4), dim3(32, 8)>>>(mask, 0);

    k_gemm<<<4096, 256, SMEM_GEMM>>>(Wbp, bbp, 0, 0);
    k_gemm<<<4096, 256, SMEM_GEMM>>>(Wbg, bbg, 0, 1);
    k_combine_t<<<dim3(N_ROWS / 32, 4), dim3(32, 8)>>>(mask, 1);

    k_gemm<<<4096, 256, SMEM_GEMM>>>(Wg, bg, 1, 2);

    k_rsq<<<64, 256>>>(mask);

    k_tri<<<dim3(4, 4, 128), 256>>>();

    k_lnstats<<<N_ROWS / 256, 256>>>();

    k_gemm_out<<<4096, 256, SMEM_GEMM2>>>(Wo, bo, lng, lnb, mask, out);
}

// round 9
// speedup vs baseline: 4.8316x; 4.8316x over previous
#include <cuda_runtime.h>
#include <cuda_fp16.h>
#include <cstdint>

#define L 512
#define NR (L * L)           // 262144
#define C 128
typedef __half f16;

// ---------------- scratch ----------------------------------------------------
__device__ f16   g_zn[(size_t)NR * C];    // z_norm fp16 [r][c]
__device__ f16   g_at[(size_t)NR * C];    // a transposed fp16 [c][i*512+k]
__device__ f16   g_bt[(size_t)NR * C];    // b transposed fp16 [c][j*512+k]
__device__ f16   g_gate[(size_t)NR * C];  // sigmoid gate fp16 [r][c]
__device__ float g_xt[(size_t)NR * C];    // contraction out fp32 [c][i*512+j]
__device__ f16   g_xn[(size_t)NR * C];    // LN-out normalized fp16 [r][c]
__device__ float g_rsq[NR];               // 1/sqrt(max(valid_k,1))
__device__ f16   g_wb[6 * C * C];         // fp16 weights: Wap,Wbp,Wag,Wbg,Wg,Wo

__device__ __forceinline__ float sigm(float x) { return 1.f / (1.f + __expf(-x)); }

// ---------------- PTX helpers (plain sm_80+ PTX only) ------------------------
__device__ __forceinline__ uint32_t smem_u32(const void* p) {
    uint32_t a;
    asm("{ .reg .u64 t; cvta.to.shared.u64 t, %1; cvt.u32.u64 %0, t; }" : "=r"(a) : "l"(p));
    return a;
}
__device__ __forceinline__ void cpa16(uint32_t dst, const void* src) {
    asm volatile("cp.async.cg.shared.global [%0], [%1], 16;" :: "r"(dst), "l"(src));
}
__device__ __forceinline__ void cpa_commit() { asm volatile("cp.async.commit_group;" ::: "memory"); }
template <int N> __device__ __forceinline__ void cpa_wait() {
    asm volatile("cp.async.wait_group %0;" :: "n"(N) : "memory");
}
__device__ __forceinline__ void ldsm4(uint32_t (&r)[4], uint32_t addr) {
    asm volatile("ldmatrix.sync.aligned.m8n8.x4.shared.b16 {%0,%1,%2,%3}, [%4];"
                 : "=r"(r[0]), "=r"(r[1]), "=r"(r[2]), "=r"(r[3]) : "r"(addr));
}
__device__ __forceinline__ void mma16816(float (&d)[4], const uint32_t (&a)[4],
                                         uint32_t b0, uint32_t b1) {
    asm volatile("mma.sync.aligned.m16n8k16.row.col.f32.f16.f16.f32 "
                 "{%0,%1,%2,%3}, {%4,%5,%6,%7}, {%8,%9}, {%0,%1,%2,%3};"
                 : "+f"(d[0]), "+f"(d[1]), "+f"(d[2]), "+f"(d[3])
                 : "r"(a[0]), "r"(a[1]), "r"(a[2]), "r"(a[3]), "r"(b0), "r"(b1));
}
// A fragment (m16k16, row-major src): rows mrow.., cols kc..
__device__ __forceinline__ uint32_t a_addr(uint32_t base, int mrow, int kc, int P, int lane) {
    return base + (uint32_t)((mrow + (lane & 15)) * P + kc + ((lane >> 4) << 3)) * 2;
}
// B fragment pair (two n8 tiles, k16), src rows = n (k-contiguous)
__device__ __forceinline__ uint32_t b_addr(uint32_t base, int nrow, int kc, int P, int lane) {
    return base + (uint32_t)((nrow + (lane & 7) + ((lane >> 4) << 3)) * P + kc +
                             (((lane >> 3) & 1) << 3)) * 2;
}

// stage a fp16 row-major [128r][128c] tile into pitched smem (pitch 136 hw)
#define PP 136
__device__ __forceinline__ void stage128(uint32_t dst, const f16* __restrict__ src, int t) {
    #pragma unroll
    for (int i = 0; i < 8; i++) {
        int idx = t + i * 256;
        int r = idx >> 4, s8 = (idx & 15) << 3;
        cpa16(dst + (uint32_t)(r * PP + s8) * 2, src + (size_t)r * C + s8);
    }
}

// warp GEMM: acc[16][4] += A(16x128, cached frags) * W^T(128x128 from smem)
__device__ __forceinline__ void gemm_w(float (*acc)[4], const uint32_t a_all[8][4],
                                       uint32_t wbase, int lane) {
    #pragma unroll
    for (int nt2 = 0; nt2 < 8; nt2++) {
        #pragma unroll
        for (int kk = 0; kk < 8; kk++) {
            uint32_t b[4];
            ldsm4(b, b_addr(wbase, nt2 * 16, kk * 16, PP, lane));
            mma16816(acc[nt2 * 2],     a_all[kk], b[0], b[1]);
            mma16816(acc[nt2 * 2 + 1], a_all[kk], b[2], b[3]);
        }
    }
}

// ---------------- K1: input LayerNorm -> fp16 -------------------------------
__global__ __launch_bounds__(256) void k_ln_in(const float* __restrict__ z,
                                               const float* __restrict__ g,
                                               const float* __restrict__ b) {
    int w = threadIdx.x >> 5, l = threadIdx.x & 31;
    size_t row = (size_t)blockIdx.x * 8 + w;
    float4 v = *(const float4*)&z[row * C + l * 4];
    float s = v.x + v.y + v.z + v.w;
    float s2 = v.x * v.x + v.y * v.y + v.z * v.z + v.w * v.w;
    #pragma unroll
    for (int o = 16; o > 0; o >>= 1) {
        s += __shfl_xor_sync(0xFFFFFFFFu, s, o);
        s2 += __shfl_xor_sync(0xFFFFFFFFu, s2, o);
    }
    float mu = s * (1.f / 128.f);
    float var = s2 * (1.f / 128.f) - mu * mu;
    float rs = rsqrtf(var + 1e-5f);
    float4 gg = *(const float4*)&g[l * 4];
    float4 bb = *(const float4*)&b[l * 4];
    __half2 p0 = __floats2half2_rn((v.x - mu) * rs * gg.x + bb.x,
                                   (v.y - mu) * rs * gg.y + bb.y);
    __half2 p1 = __floats2half2_rn((v.z - mu) * rs * gg.z + bb.z,
                                   (v.w - mu) * rs * gg.w + bb.w);
    uint2 pk = make_uint2(*reinterpret_cast<uint32_t*>(&p0), *reinterpret_cast<uint32_t*>(&p1));
    *reinterpret_cast<uint2*>(&g_zn[row * C + l * 4]) = pk;
}

// ---------------- K2: rsq ----------------------------------------------------
__global__ void k_rsq(const float* __restrict__ mask) {
    __shared__ float mi[8][512];
    int i0 = blockIdx.x * 8;
    int tid = threadIdx.x;
    for (int idx = tid; idx < 8 * 512; idx += 256)
        mi[idx >> 9][idx & 511] = mask[(size_t)(i0 + (idx >> 9)) * L + (idx & 511)];
    __syncthreads();
    for (int j = tid; j < L; j += 256) {
        float s[8];
        #pragma unroll
        for (int ii = 0; ii < 8; ii++) s[ii] = 0.f;
        for (int k = 0; k < L; k += 4) {
            float4 m4 = *(const float4*)&mask[(size_t)j * L + k];
            float mv[4] = {m4.x, m4.y, m4.z, m4.w};
            #pragma unroll
            for (int q = 0; q < 4; q++)
                #pragma unroll
                for (int ii = 0; ii < 8; ii++) s[ii] = fmaf(mi[ii][k + q], mv[q], s[ii]);
        }
        #pragma unroll
        for (int ii = 0; ii < 8; ii++)
            g_rsq[(size_t)(i0 + ii) * L + j] = rsqrtf(fmaxf(s[ii], 1.f));
    }
}

// ---------------- K0: weights fp32 -> fp16 -----------------------------------
__global__ void k_wconv(const float* __restrict__ Wap, const float* __restrict__ Wbp,
                        const float* __restrict__ Wag, const float* __restrict__ Wbg,
                        const float* __restrict__ Wg,  const float* __restrict__ Wo) {
    const float* src[6] = {Wap, Wbp, Wag, Wbg, Wg, Wo};
    int m = blockIdx.y;
    const float* W = src[m];
    int idx = (blockIdx.x * 256 + threadIdx.x) * 4;
    float4 v = *(const float4*)&W[idx];
    __half2 p0 = __floats2half2_rn(v.x, v.y);
    __half2 p1 = __floats2half2_rn(v.z, v.w);
    *(uint2*)&g_wb[m * 16384 + idx] =
        make_uint2(*reinterpret_cast<uint32_t*>(&p0), *reinterpret_cast<uint32_t*>(&p1));
}

// ---------------- K3: fused projections (HMMA) -------------------------------
#define PROJ_SMEM (34816 * 2 + 5 * 128 * 4)

__global__ __launch_bounds__(256) void k_proj(
    const float* __restrict__ bap, const float* __restrict__ bag,
    const float* __restrict__ bbp, const float* __restrict__ bbg,
    const float* __restrict__ bgp, const float* __restrict__ mask) {
    extern __shared__ char sm[];
    const uint32_t sb = smem_u32(sm);
    const uint32_t Xs = sb, Ws = sb + 34816;
    f16* stage = (f16*)(sm + 34816);    // aliases Ws (used after GEMMs)
    float* sbias = (float*)(sm + 69632);
    const int t = threadIdx.x, lane = t & 31, w = t >> 5;
    const size_t r0 = (size_t)blockIdx.x * 128;

    stage128(Xs, g_zn + r0 * C, t);
    cpa_commit();
    if (t < 128) {
        sbias[t] = bap[t]; sbias[128 + t] = bag[t]; sbias[256 + t] = bbp[t];
        sbias[384 + t] = bbg[t]; sbias[512 + t] = bgp[t];
    }
    cpa_wait<0>();
    __syncthreads();

    uint32_t a_all[8][4];
    #pragma unroll
    for (int kk = 0; kk < 8; kk++)
        ldsm4(a_all[kk], a_addr(Xs, w * 16, kk * 16, PP, lane));

    const float m0 = mask[r0 + w * 16 + (lane >> 2)];
    const float m1 = mask[r0 + w * 16 + 8 + (lane >> 2)];

    #pragma unroll 1
    for (int pass = 0; pass < 2; pass++) {
        stage128(Ws, g_wb + (size_t)pass * 16384, t);       // Wap / Wbp
        cpa_commit(); cpa_wait<0>(); __syncthreads();
        float accP[16][4];
        #pragma unroll
        for (int i = 0; i < 16; i++)
            #pragma unroll
            for (int q = 0; q < 4; q++) accP[i][q] = 0.f;
        gemm_w(accP, a_all, Ws, lane);
        __syncthreads();

        stage128(Ws, g_wb + (size_t)(2 + pass) * 16384, t); // Wag / Wbg
        cpa_commit(); cpa_wait<0>(); __syncthreads();
        float accG[16][4];
        #pragma unroll
        for (int i = 0; i < 16; i++)
            #pragma unroll
            for (int q = 0; q < 4; q++) accG[i][q] = 0.f;
        gemm_w(accG, a_all, Ws, lane);
        __syncthreads();

        const float* bP = sbias + pass * 256;
        const float* bG = bP + 128;
        f16* outg = pass ? g_bt : g_at;

        #pragma unroll
        for (int nt = 0; nt < 16; nt++) {
            int col = nt * 8 + (lane & 3) * 2;
            int row0 = w * 16 + (lane >> 2), row1 = row0 + 8;
            float bp0 = bP[col], bp1 = bP[col + 1];
            float bg0 = bG[col], bg1 = bG[col + 1];
            stage[col * 128 + row0]       = __float2half((accP[nt][0] + bp0) * sigm(accG[nt][0] + bg0) * m0);
            stage[(col + 1) * 128 + row0] = __float2half((accP[nt][1] + bp1) * sigm(accG[nt][1] + bg1) * m0);
            stage[col * 128 + row1]       = __float2half((accP[nt][2] + bp0) * sigm(accG[nt][2] + bg0) * m1);
            stage[(col + 1) * 128 + row1] = __float2half((accP[nt][3] + bp1) * sigm(accG[nt][3] + bg1) * m1);
        }
        __syncthreads();
        #pragma unroll
        for (int i = 0; i < 8; i++) {
            int idx = t + i * 256, cc = idx >> 4, seg = (idx & 15) << 3;
            *(uint4*)&outg[(size_t)cc * NR + r0 + seg] = *(const uint4*)&stage[cc * 128 + seg];
        }
        __syncthreads();
    }

    // gate pass: sigm(zn Wg + bg), row-major
    stage128(Ws, g_wb + 4 * 16384, t);
    cpa_commit(); cpa_wait<0>(); __syncthreads();
    float accP[16][4];
    #pragma unroll
    for (int i = 0; i < 16; i++)
        #pragma unroll
        for (int q = 0; q < 4; q++) accP[i][q] = 0.f;
    gemm_w(accP, a_all, Ws, lane);

    #pragma unroll
    for (int nt = 0; nt < 16; nt++) {
        int col = nt * 8 + (lane & 3) * 2;
        int row0 = w * 16 + (lane >> 2), row1 = row0 + 8;
        float b0 = sbias[512 + col], b1 = sbias[512 + col + 1];
        __half2 h0 = __floats2half2_rn(sigm(accP[nt][0] + b0), sigm(accP[nt][1] + b1));
        __half2 h1 = __floats2half2_rn(sigm(accP[nt][2] + b0), sigm(accP[nt][3] + b1));
        *(uint32_t*)&g_gate[(r0 + row0) * C + col] = *reinterpret_cast<uint32_t*>(&h0);
        *(uint32_t*)&g_gate[(r0 + row1) * C + col] = *reinterpret_cast<uint32_t*>(&h1);
    }
}

// ---------------- K4: triangle contraction (HMMA, per channel) ---------------
#define PT 72
#define TRI_SMEM (4 * 128 * PT * 2)   // 73728

__global__ __launch_bounds__(256) void k_tri() {
    extern __shared__ char sm[];
    const uint32_t sb = smem_u32(sm);
    const int t = threadIdx.x, lane = t & 31, w = t >> 5;
    const int c = blockIdx.z, i0 = blockIdx.y * 128, j0 = blockIdx.x * 128;
    const f16* A = g_at + (size_t)c * NR + (size_t)i0 * L;
    const f16* Bg = g_bt + (size_t)c * NR + (size_t)j0 * L;
    const uint32_t Ab[2] = {sb, sb + 18432};
    const uint32_t Bb[2] = {sb + 36864, sb + 55296};

    // preload chunk 0
    {
        #pragma unroll
        for (int i = 0; i < 4; i++) {
            int idx = t + i * 256, r = idx >> 3, s = (idx & 7) << 3;
            cpa16(Ab[0] + (uint32_t)(r * PT + s) * 2, A + (size_t)r * L + s);
        }
        #pragma unroll
        for (int i = 0; i < 4; i++) {
            int idx = t + i * 256, r = idx >> 3, s = (idx & 7) << 3;
            cpa16(Bb[0] + (uint32_t)(r * PT + s) * 2, Bg + (size_t)r * L + s);
        }
        cpa_commit();
    }

    float acc[16][4];
    #pragma unroll
    for (int i = 0; i < 16; i++)
        #pragma unroll
        for (int q = 0; q < 4; q++) acc[i][q] = 0.f;
    const int wi = (w & 3) * 32, wj = (w >> 2) * 64;

    for (int kb = 0; kb < 8; kb++) {
        int b = kb & 1;
        if (kb < 7) {
            int nb = b ^ 1;
            #pragma unroll
            for (int i = 0; i < 4; i++) {
                int idx = t + i * 256, r = idx >> 3, s = (idx & 7) << 3;
                cpa16(Ab[nb] + (uint32_t)(r * PT + s) * 2, A + (size_t)r * L + (kb + 1) * 64 + s);
            }
            #pragma unroll
            for (int i = 0; i < 4; i++) {
                int idx = t + i * 256, r = idx >> 3, s = (idx & 7) << 3;
                cpa16(Bb[nb] + (uint32_t)(r * PT + s) * 2, Bg + (size_t)r * L + (kb + 1) * 64 + s);
            }
            cpa_commit();
            cpa_wait<1>();
        } else {
            cpa_wait<0>();
        }
        __syncthreads();
        #pragma unroll
        for (int kk = 0; kk < 4; kk++) {
            uint32_t a0[4], a1[4];
            ldsm4(a0, a_addr(Ab[b], wi, kk * 16, PT, lane));
            ldsm4(a1, a_addr(Ab[b], wi + 16, kk * 16, PT, lane));
            #pragma unroll
            for (int nt2 = 0; nt2 < 4; nt2++) {
                uint32_t bb[4];
                ldsm4(bb, b_addr(Bb[b], wj + nt2 * 16, kk * 16, PT, lane));
                mma16816(acc[nt2 * 2],         a0, bb[0], bb[1]);
                mma16816(acc[nt2 * 2 + 1],     a0, bb[2], bb[3]);
                mma16816(acc[8 + nt2 * 2],     a1, bb[0], bb[1]);
                mma16816(acc[8 + nt2 * 2 + 1], a1, bb[2], bb[3]);
            }
        }
        __syncthreads();
    }

    float* xp = g_xt + (size_t)c * NR;
    #pragma unroll
    for (int mt = 0; mt < 2; mt++) {
        int row0 = i0 + wi + mt * 16 + (lane >> 2);
        #pragma unroll
        for (int nt = 0; nt < 8; nt++) {
            int col = j0 + wj + nt * 8 + (lane & 3) * 2;
            float* d = acc[mt * 8 + nt];
            size_t o0 = (size_t)row0 * L + col;
            size_t o1 = (size_t)(row0 + 8) * L + col;
            float2 rv0 = *(const float2*)&g_rsq[o0];
            float2 rv1 = *(const float2*)&g_rsq[o1];
            *(float2*)&xp[o0] = make_float2(d[0] * rv0.x, d[1] * rv0.y);
            *(float2*)&xp[o1] = make_float2(d[2] * rv1.x, d[3] * rv1.y);
        }
    }
}

// ---------------- K5: LN-out stats + normalize + transpose -> fp16 [r][c] ----
__global__ __launch_bounds__(128) void k_lnT(const float* __restrict__ lng,
                                             const float* __restrict__ lnb) {
    extern __shared__ float raw[];  // [128][132]
    const int t = threadIdx.x, w = t >> 5, l = t & 31;
    const size_t r0 = (size_t)blockIdx.x * 128;
    #pragma unroll 4
    for (int cc = 0; cc < 32; cc++) {
        int c = w * 32 + cc;
        float4 v = *(const float4*)&g_xt[(size_t)c * NR + r0 + l * 4];
        *(float4*)&raw[c * 132 + l * 4] = v;
    }
    __syncthreads();
    float s = 0.f, s2 = 0.f;
    #pragma unroll 8
    for (int c = 0; c < C; c++) {
        float v = raw[c * 132 + t];
        s += v; s2 += v * v;
    }
    float mu = s * (1.f / 128.f);
    float var = s2 * (1.f / 128.f) - mu * mu;
    float rs = rsqrtf(var + 1e-5f);
    f16* xr = g_xn + (r0 + t) * C;
    #pragma unroll
    for (int seg = 0; seg < 16; seg++) {
        uint32_t u[4];
        #pragma unroll
        for (int q = 0; q < 4; q++) {
            int c = seg * 8 + q * 2;
            float v0 = (raw[c * 132 + t] - mu) * rs * lng[c] + lnb[c];
            float v1 = (raw[(c + 1) * 132 + t] - mu) * rs * lng[c + 1] + lnb[c + 1];
            __half2 p = __floats2half2_rn(v0, v1);
            u[q] = *reinterpret_cast<uint32_t*>(&p);
        }
        *reinterpret_cast<uint4*>(xr + seg * 8) = make_uint4(u[0], u[1], u[2], u[3]);
    }
}

// ---------------- K6: output GEMM + gate epilogue (HMMA) ---------------------
#define OUT_SMEM (34816 * 2 + 512)

__global__ __launch_bounds__(256) void k_out(const float* __restrict__ bo,
                                             const float* __restrict__ mask,
                                             float* __restrict__ OUT) {
    extern __shared__ char sm[];
    const uint32_t sb = smem_u32(sm);
    const uint32_t Xs = sb, Ws = sb + 34816;
    float* sbo = (float*)(sm + 69632);
    const int t = threadIdx.x, lane = t & 31, w = t >> 5;
    const size_t r0 = (size_t)blockIdx.x * 128;

    stage128(Xs, g_xn + r0 * C, t);
    stage128(Ws, g_wb + 5 * 16384, t);
    cpa_commit();
    if (t < 128) sbo[t] = bo[t];
    cpa_wait<0>();
    __syncthreads();

    uint32_t a_all[8][4];
    #pragma unroll
    for (int kk = 0; kk < 8; kk++)
        ldsm4(a_all[kk], a_addr(Xs, w * 16, kk * 16, PP, lane));

    float acc[16][4];
    #pragma unroll
    for (int i = 0; i < 16; i++)
        #pragma unroll
        for (int q = 0; q < 4; q++) acc[i][q] = 0.f;
    gemm_w(acc, a_all, Ws, lane);

    const float m0 = mask[r0 + w * 16 + (lane >> 2)];
    const float m1 = mask[r0 + w * 16 + 8 + (lane >> 2)];
    #pragma unroll
    for (int nt = 0; nt < 16; nt++) {
        int col = nt * 8 + (lane & 3) * 2;
        int row0 = w * 16 + (lane >> 2), row1 = row0 + 8;
        float b0 = sbo[col], b1 = sbo[col + 1];
        __half2 gg0 = *(const __half2*)&g_gate[(r0 + row0) * C + col];
        __half2 gg1 = *(const __half2*)&g_gate[(r0 + row1) * C + col];
        float2 o0 = make_float2((acc[nt][0] + b0) * __low2float(gg0) * m0,
                                (acc[nt][1] + b1) * __high2float(gg0) * m0);
        float2 o1 = make_float2((acc[nt][2] + b0) * __low2float(gg1) * m1,
                                (acc[nt][3] + b1) * __high2float(gg1) * m1);
        *(float2*)&OUT[(r0 + row0) * C + col] = o0;
        *(float2*)&OUT[(r0 + row1) * C + col] = o1;
    }
}

// ---------------- launch -----------------------------------------------------
extern "C" void kernel_launch(void* const* d_in, const int* in_sizes, int n_in,
                              void* d_out, int out_size) {
    const float* z       = (const float*)d_in[0];
    const float* mask    = (const float*)d_in[1];
    const float* ln_in_g = (const float*)d_in[2];
    const float* ln_in_b = (const float*)d_in[3];
    const float* Wap = (const float*)d_in[4],  *bap = (const float*)d_in[5];
    const float* Wbp = (const float*)d_in[6],  *bbp = (const float*)d_in[7];
    const float* Wag = (const float*)d_in[8],  *bag = (const float*)d_in[9];
    const float* Wbg = (const float*)d_in[10], *bbg = (const float*)d_in[11];
    const float* lng = (const float*)d_in[12], *lnb = (const float*)d_in[13];
    const float* Wo  = (const float*)d_in[14], *bo  = (const float*)d_in[15];
    const float* Wg  = (const float*)d_in[16], *bg  = (const float*)d_in[17];
    float* out = (float*)d_out;

    cudaFuncSetAttribute(k_proj, cudaFuncAttributeMaxDynamicSharedMemorySize, PROJ_SMEM);
    cudaFuncSetAttribute(k_tri,  cudaFuncAttributeMaxDynamicSharedMemorySize, TRI_SMEM);
    cudaFuncSetAttribute(k_lnT,  cudaFuncAttributeMaxDynamicSharedMemorySize, 128 * 132 * 4);
    cudaFuncSetAttribute(k_out,  cudaFuncAttributeMaxDynamicSharedMemorySize, OUT_SMEM);

    k_ln_in<<<NR / 8, 256>>>(z, ln_in_g, ln_in_b);
    k_rsq<<<64, 256>>>(mask);
    k_wconv<<<dim3(16, 6), 256>>>(Wap, Wbp, Wag, Wbg, Wg, Wo);
    k_proj<<<NR / 128, 256, PROJ_SMEM>>>(bap, bag, bbp, bbg, bg, mask);
    k_tri<<<dim3(4, 4, 128), 256, TRI_SMEM>>>();
    k_lnT<<<NR / 128, 128, 128 * 132 * 4>>>(lng, lnb);
    k_out<<<NR / 128, 256, OUT_SMEM>>>(bo, mask, out);
}